// round 14
// baseline (speedup 1.0000x reference)
#include <cuda_runtime.h>
#include <math.h>

// ---------------- problem constants ----------------
#define KS    11
#define HI    384
#define HO    512
#define HOUT  (HO - KS + 1)     // 502
#define TW    32                // tile width (outputs)
#define TH    72                // tile height (outputs)
#define PW    (TW + KS - 1)     // 42
#define PH    (TH + KS - 1)     // 82
#define SR    42                // s12 ring rows
#define SW    43                // s12 row stride (ull), odd -> conflict-free row walks
#define HS    33                // hbuf row stride (elements)
#define NTX   ((HOUT + TW - 1) / TW)   // 16
#define NTY   ((HOUT + TH - 1) / TH)   // 7
#define NTHREADS 384

typedef unsigned long long ull;

// Gaussian weights (sigma=1.5, ks=11), double-normalized, rounded to f32.
#define GW0  0.0010283801f
#define GW1  0.0075987582f
#define GW2  0.0360007722f
#define GW3  0.1093606884f
#define GW4  0.2130055383f
#define GW5  0.2660117256f

__device__ double        g_accum = 0.0;
__device__ unsigned int  g_count = 0;

// ---------------- f32x2 packed helpers ----------------
__device__ __forceinline__ ull splat2(float g) {
    ull r; asm("mov.b64 %0, {%1, %1};" : "=l"(r) : "f"(g)); return r;
}
__device__ __forceinline__ void up2(ull v, float& lo, float& hi) {
    asm("mov.b64 {%0, %1}, %2;" : "=f"(lo), "=f"(hi) : "l"(v));
}
__device__ __forceinline__ ull pk2(float lo, float hi) {
    ull r; asm("mov.b64 %0, {%1, %2};" : "=l"(r) : "f"(lo), "f"(hi)); return r;
}
__device__ __forceinline__ ull pfma(ull a, ull b, ull c) {
    ull d; asm("fma.rn.f32x2 %0, %1, %2, %3;" : "=l"(d) : "l"(a), "l"(b), "l"(c)); return d;
}
__device__ __forceinline__ ull pmul(ull a, ull b) {
    ull d; asm("mul.rn.f32x2 %0, %1, %2;" : "=l"(d) : "l"(a), "l"(b)); return d;
}

#define GWC(k) ((k) < 6 ? (k) : 10 - (k))

// ---- dynamic smem layout (bytes) ----
#define OFF_S12   0                                  // ull [SR][SW] = 14448 (ring)
#define OFF_HMU   (OFF_S12 + SR * SW * 8)            // ull [PH][HS] = 21648 (mu1h, mu2h)
#define OFF_HSX   (OFF_HMU + PH * HS * 8)            // ull [PH][HS] = 21648 (x11h+x22h, x12h)
#define OFF_TBL   (OFF_HSX + PH * HS * 8)
#define OFF_RED   (OFF_TBL + (PH * 4 + PW * 4) * 4)  // tables = 1984
#define SMEM_BYTES (OFF_RED + 64)                    // 59792 B -> 3 CTAs/SM (179KB)

// ---------------- single fused kernel ----------------
__global__ void __launch_bounds__(NTHREADS, 3)
ssim_tile_kernel(const float* __restrict__ input,   // [96, 384, 384]
                 const float* __restrict__ target,  // [96, 512, 512]
                 float* __restrict__ out,
                 long long count, unsigned int nblocks)
{
    extern __shared__ char smem[];
    ull   (*s12)[SW] = (ull (*)[SW])(smem + OFF_S12);
    ull   (*hmu)[HS] = (ull (*)[HS])(smem + OFF_HMU);
    ull   (*hsx)[HS] = (ull (*)[HS])(smem + OFF_HSX);
    int   *riy0 = (int*)  (smem + OFF_TBL);
    int   *riy1 = riy0 + PH;
    float *rwy  = (float*)(riy1 + PH);
    int   *rgy  = (int*)  (rwy + PH);
    int   *cix0 = rgy + PH;
    int   *cix1 = cix0 + PW;
    float *cwx  = (float*)(cix1 + PW);
    int   *cgx  = (int*)  (cwx + PW);
    float *redbuf = (float*)(smem + OFF_RED);

    const int img = blockIdx.z;
    const int ty0 = blockIdx.y * TH;
    const int tx0 = blockIdx.x * TW;
    const int tid = threadIdx.x;

    const float GW[6] = {GW0, GW1, GW2, GW3, GW4, GW5};
    ull CS[6];
    #pragma unroll
    for (int k = 0; k < 6; k++) CS[k] = splat2(GW[k]);

    const float* inp = input  + (size_t)img * (HI * HI);
    const float* tgt = target + (size_t)img * (HO * HO);

    // ---- build bilinear tables ----
    if (tid < PH) {
        int gy = min(ty0 + tid, HO - 1);
        int py = gy * (HI - 1);
        int iy0 = py / (HO - 1);
        riy0[tid] = iy0 * HI;
        riy1[tid] = min(iy0 + 1, HI - 1) * HI;
        rwy[tid]  = (float)(py - iy0 * (HO - 1)) * (1.0f / (float)(HO - 1));
        rgy[tid]  = gy * HO;
    }
    if (tid >= 128 && tid < 128 + PW) {
        int c = tid - 128;
        int gx = min(tx0 + c, HO - 1);
        int px = gx * (HI - 1);
        int ix0 = px / (HO - 1);
        cix0[c] = ix0;
        cix1[c] = min(ix0 + 1, HI - 1);
        cwx[c]  = (float)(px - ix0 * (HO - 1)) * (1.0f / (float)(HO - 1));
        cgx[c]  = gx;
    }
    __syncthreads();

    // ======== two chunks: s12 is a 42-row ring ========
    // chunk 0: patch rows 0..41 -> slots 0..41
    // chunk 1: patch rows 42..81 -> slots 0..39 (H of chunk 0 done by then)
    #pragma unroll 1
    for (int chunk = 0; chunk < 2; chunk++) {
        const int r0    = chunk ? SR : 0;
        const int nrows = chunk ? (PH - SR) : SR;    // 40 : 42

        // ---- load chunk: target direct, img1 bilinear via tables ----
        for (int e = tid; e < nrows * PW; e += NTHREADS) {
            int rl = e / PW;            // ring slot
            int c  = e - rl * PW;
            int r  = r0 + rl;           // patch row

            float t2 = tgt[rgy[r] + cgx[c]];

            int   y0 = riy0[r], y1 = riy1[r];
            float wy = rwy[r];
            int   x0 = cix0[c], x1 = cix1[c];
            float wx = cwx[c];

            float a  = inp[y0 + x0];
            float b  = inp[y0 + x1];
            float cc = inp[y1 + x0];
            float d  = inp[y1 + x1];
            float top = a  + (b - a)  * wx;
            float bot = cc + (d - cc) * wx;
            float v1  = top + (bot - top) * wy;

            s12[rl][c] = pk2(v1, t2);
        }
        __syncthreads();

        // ---- horizontal pass for this chunk's rows (8 outputs/task) ----
        const int ntasks = nrows * 4;

        for (int t = tid; t < ntasks; t += NTHREADS) {
            int g  = t / nrows;         // col group 0..3
            int rl = t - g * nrows;     // ring slot
            int r  = r0 + rl;           // patch row (hbuf row)
            int c0 = g << 3;

            ull aM[8], aSX[8];
            #pragma unroll
            for (int o = 0; o < 8; o++) { aM[o] = 0; aSX[o] = 0; }

            #pragma unroll
            for (int j = 0; j < 18; j++) {
                ull pk = s12[rl][c0 + j];
                float p1, p2;
                up2(pk, p1, p2);
                ull sq = pmul(pk, pk);
                float s1, s2;
                up2(sq, s1, s2);
                ull sx = pk2(s1 + s2, p1 * p2);   // (p1^2+p2^2, p1*p2)
                #pragma unroll
                for (int o = 0; o < 8; o++) {
                    int k = j - o;
                    if (k >= 0 && k < KS) {
                        aM[o]  = pfma(pk, CS[GWC(k)], aM[o]);
                        aSX[o] = pfma(sx, CS[GWC(k)], aSX[o]);
                    }
                }
            }
            #pragma unroll
            for (int o = 0; o < 8; o++) {
                hmu[r][c0 + o] = aM[o];
                hsx[r][c0 + o] = aSX[o];
            }
        }
        __syncthreads();
    }

    // ---- vertical pass: 12 warps x 6 rows/thread, 16-tap window, linear hbuf ----
    const int lx = tid & 31;
    const int w  = tid >> 5;
    const int v0 = w * 6;               // warp w -> output rows 6w..6w+5
    const int gx = tx0 + lx;
    const float C1 = 1e-4f;
    const float C2 = 9e-4f;
    float lsum = 0.f;

    ull aM[6], aSX[6];
    #pragma unroll
    for (int o = 0; o < 6; o++) { aM[o] = 0; aSX[o] = 0; }

    #pragma unroll
    for (int rel = 0; rel < 16; rel++) {
        int rr = v0 + rel;
        ull vM  = hmu[rr][lx];
        ull vSX = hsx[rr][lx];
        #pragma unroll
        for (int o = 0; o < 6; o++) {
            int k = rel - o;
            if (k >= 0 && k < KS) {
                aM[o]  = pfma(vM,  CS[GWC(k)], aM[o]);
                aSX[o] = pfma(vSX, CS[GWC(k)], aSX[o]);
            }
        }
    }

    // ---- SSIM map + local sum ----
    #pragma unroll
    for (int o = 0; o < 6; o++) {
        int gy = ty0 + v0 + o;
        if (gy < HOUT && gx < HOUT) {
            float mu1, mu2, xsum, x12;
            up2(aM[o], mu1, mu2);
            up2(aSX[o], xsum, x12);
            float mu1sq = mu1 * mu1;
            float mu2sq = mu2 * mu2;
            float mu12  = mu1 * mu2;
            float sigsum = xsum - mu1sq - mu2sq;  // sigma1_sq + sigma2_sq
            float sig12  = x12  - mu12;
            float v1 = 2.0f * sig12 + C2;
            float v2 = sigsum + C2;
            float num = (2.0f * mu12 + C1) * v1;
            float den = (mu1sq + mu2sq + C1) * v2;
            lsum += __fdividef(num, den);
        }
    }

    // ---- block reduction (12 warps) ----
    #pragma unroll
    for (int off = 16; off > 0; off >>= 1)
        lsum += __shfl_down_sync(0xFFFFFFFFu, lsum, off);
    if (lx == 0) redbuf[w] = lsum;
    __syncthreads();
    if (tid == 0) {
        float v = 0.f;
        #pragma unroll
        for (int ww = 0; ww < 12; ww++) v += redbuf[ww];
        atomicAdd(&g_accum, (double)v);
        __threadfence();
        unsigned int old = atomicAdd(&g_count, 1u);
        if (old == nblocks - 1u) {
            double mean = g_accum / (double)count;
            double loss = 1.0 - mean;
            if (loss < 0.0) loss = 0.0;
            if (loss > 1.0) loss = 1.0;
            out[0] = (float)loss;
            g_accum = 0.0;
            g_count = 0u;
        }
    }
}

extern "C" void kernel_launch(void* const* d_in, const int* in_sizes, int n_in,
                              void* d_out, int out_size) {
    const float* input  = (const float*)d_in[0];
    const float* target = (const float*)d_in[1];
    int sz0 = in_sizes[0], sz1 = in_sizes[1];
    if (sz0 > sz1) {
        const float* t = input; input = target; target = t;
        int ts = sz0; sz0 = sz1; sz1 = ts;
    }
    int n_img = sz0 / (HI * HI);   // 96

    static bool attr_set = false;
    if (!attr_set) {
        cudaFuncSetAttribute(ssim_tile_kernel,
                             cudaFuncAttributeMaxDynamicSharedMemorySize, SMEM_BYTES);
        attr_set = true;
    }

    dim3 grid(NTX, NTY, n_img);
    unsigned int nblocks = NTX * NTY * (unsigned int)n_img;
    long long count = (long long)n_img * HOUT * HOUT;

    ssim_tile_kernel<<<grid, NTHREADS, SMEM_BYTES>>>(input, target, (float*)d_out,
                                                     count, nblocks);
}

// round 15
// speedup vs baseline: 1.0523x; 1.0523x over previous
#include <cuda_runtime.h>
#include <math.h>

// ---------------- problem constants ----------------
#define KS    11
#define HI    384
#define HO    512
#define HOUT  (HO - KS + 1)     // 502
#define TW    32                // tile width (outputs)
#define TH    64                // tile height (outputs)
#define PW    (TW + KS - 1)     // 42
#define PH    (TH + KS - 1)     // 74
#define SR    42                // s12 ring rows
#define SW    43                // s12 row stride (ull), odd -> conflict-free row walks
#define HS    33                // hbuf row stride (elements)
#define NTX   ((HOUT + TW - 1) / TW)   // 16
#define NTY   ((HOUT + TH - 1) / TH)   // 8

typedef unsigned long long ull;

// Gaussian weights (sigma=1.5, ks=11), double-normalized, rounded to f32.
#define GW0  0.0010283801f
#define GW1  0.0075987582f
#define GW2  0.0360007722f
#define GW3  0.1093606884f
#define GW4  0.2130055383f
#define GW5  0.2660117256f

__device__ double        g_accum = 0.0;
__device__ unsigned int  g_count = 0;

// ---------------- f32x2 packed helpers ----------------
__device__ __forceinline__ ull splat2(float g) {
    ull r; asm("mov.b64 %0, {%1, %1};" : "=l"(r) : "f"(g)); return r;
}
__device__ __forceinline__ void up2(ull v, float& lo, float& hi) {
    asm("mov.b64 {%0, %1}, %2;" : "=f"(lo), "=f"(hi) : "l"(v));
}
__device__ __forceinline__ ull pk2(float lo, float hi) {
    ull r; asm("mov.b64 %0, {%1, %2};" : "=l"(r) : "f"(lo), "f"(hi)); return r;
}
__device__ __forceinline__ ull pfma(ull a, ull b, ull c) {
    ull d; asm("fma.rn.f32x2 %0, %1, %2, %3;" : "=l"(d) : "l"(a), "l"(b), "l"(c)); return d;
}
__device__ __forceinline__ ull pmul(ull a, ull b) {
    ull d; asm("mul.rn.f32x2 %0, %1, %2;" : "=l"(d) : "l"(a), "l"(b)); return d;
}

// bf16x2 <-> f32x2: bf16 is the top 16 bits of f32.
// pack: (lo,hi) f32 pair -> uint bf16x2 (lo in bits[0:16), hi in bits[16:32))
__device__ __forceinline__ unsigned f2_to_b2(ull v) {
    float lo, hi; up2(v, lo, hi);
    unsigned r;
    asm("cvt.rn.bf16x2.f32 %0, %1, %2;" : "=r"(r) : "f"(hi), "f"(lo));
    return r;
}
// unpack: uint bf16x2 -> ull f32x2 (exact: shift into f32 exponent position)
__device__ __forceinline__ ull b2_to_f2(unsigned v) {
    unsigned lo = v << 16;
    unsigned hi = v & 0xFFFF0000u;
    ull r; asm("mov.b64 %0, {%1, %2};" : "=l"(r) : "r"(lo), "r"(hi));
    return r;
}

#define GWC(k) ((k) < 6 ? (k) : 10 - (k))

// ---- dynamic smem layout (bytes) ----
#define OFF_S12   0                                  // ull  [SR][SW] = 14448 (ring)
#define OFF_HMU   (OFF_S12 + SR * SW * 8)            // uint [PH][HS] =  9768 (bf16x2 mu1,mu2)
#define OFF_HSX   (OFF_HMU + PH * HS * 4)            // uint [PH][HS] =  9768 (bf16x2 xsum,x12)
#define OFF_TBL   (OFF_HSX + PH * HS * 4)
#define OFF_RED   (OFF_TBL + (PH * 4 + PW * 4) * 4)  // tables = 1856
#define SMEM_BYTES (OFF_RED + 64)                    // 35904 B; reg-bound 4 CTAs/SM

// ---------------- single fused kernel ----------------
__global__ void __launch_bounds__(256, 4)
ssim_tile_kernel(const float* __restrict__ input,   // [96, 384, 384]
                 const float* __restrict__ target,  // [96, 512, 512]
                 float* __restrict__ out,
                 long long count, unsigned int nblocks)
{
    extern __shared__ char smem[];
    ull      (*s12)[SW] = (ull (*)[SW])(smem + OFF_S12);
    unsigned (*hmu)[HS] = (unsigned (*)[HS])(smem + OFF_HMU);
    unsigned (*hsx)[HS] = (unsigned (*)[HS])(smem + OFF_HSX);
    int   *riy0 = (int*)  (smem + OFF_TBL);
    int   *riy1 = riy0 + PH;
    float *rwy  = (float*)(riy1 + PH);
    int   *rgy  = (int*)  (rwy + PH);
    int   *cix0 = rgy + PH;
    int   *cix1 = cix0 + PW;
    float *cwx  = (float*)(cix1 + PW);
    int   *cgx  = (int*)  (cwx + PW);
    float *redbuf = (float*)(smem + OFF_RED);

    const int img = blockIdx.z;
    const int ty0 = blockIdx.y * TH;
    const int tx0 = blockIdx.x * TW;
    const int tid = threadIdx.x;

    const float GW[6] = {GW0, GW1, GW2, GW3, GW4, GW5};
    ull CS[6];
    #pragma unroll
    for (int k = 0; k < 6; k++) CS[k] = splat2(GW[k]);

    const float* inp = input  + (size_t)img * (HI * HI);
    const float* tgt = target + (size_t)img * (HO * HO);

    // ---- build bilinear tables ----
    if (tid < PH) {
        int gy = min(ty0 + tid, HO - 1);
        int py = gy * (HI - 1);
        int iy0 = py / (HO - 1);
        riy0[tid] = iy0 * HI;
        riy1[tid] = min(iy0 + 1, HI - 1) * HI;
        rwy[tid]  = (float)(py - iy0 * (HO - 1)) * (1.0f / (float)(HO - 1));
        rgy[tid]  = gy * HO;
    }
    if (tid >= 128 && tid < 128 + PW) {
        int c = tid - 128;
        int gx = min(tx0 + c, HO - 1);
        int px = gx * (HI - 1);
        int ix0 = px / (HO - 1);
        cix0[c] = ix0;
        cix1[c] = min(ix0 + 1, HI - 1);
        cwx[c]  = (float)(px - ix0 * (HO - 1)) * (1.0f / (float)(HO - 1));
        cgx[c]  = gx;
    }
    __syncthreads();

    // ======== two chunks: s12 is a 42-row ring ========
    #pragma unroll 1
    for (int chunk = 0; chunk < 2; chunk++) {
        const int r0    = chunk ? SR : 0;
        const int nrows = chunk ? (PH - SR) : SR;    // 32 : 42

        // ---- load chunk: target direct, img1 bilinear via tables ----
        for (int e = tid; e < nrows * PW; e += 256) {
            int rl = e / PW;            // ring slot
            int c  = e - rl * PW;
            int r  = r0 + rl;           // patch row

            float t2 = tgt[rgy[r] + cgx[c]];

            int   y0 = riy0[r], y1 = riy1[r];
            float wy = rwy[r];
            int   x0 = cix0[c], x1 = cix1[c];
            float wx = cwx[c];

            float a  = inp[y0 + x0];
            float b  = inp[y0 + x1];
            float cc = inp[y1 + x0];
            float d  = inp[y1 + x1];
            float top = a  + (b - a)  * wx;
            float bot = cc + (d - cc) * wx;
            float v1  = top + (bot - top) * wy;

            s12[rl][c] = pk2(v1, t2);
        }
        __syncthreads();

        // ---- horizontal pass: 8 outputs/task, 18-tap sliding window ----
        const int ntasks = nrows * 4;

        for (int t = tid; t < ntasks; t += 256) {
            int g  = t / nrows;         // col group 0..3
            int rl = t - g * nrows;     // ring slot
            int r  = r0 + rl;           // patch row (hbuf row)
            int c0 = g << 3;

            ull aM[8], aSX[8];
            #pragma unroll
            for (int o = 0; o < 8; o++) { aM[o] = 0; aSX[o] = 0; }

            #pragma unroll
            for (int j = 0; j < 18; j++) {
                ull pk = s12[rl][c0 + j];
                float p1, p2;
                up2(pk, p1, p2);
                ull sq = pmul(pk, pk);
                float s1, s2;
                up2(sq, s1, s2);
                ull sx = pk2(s1 + s2, p1 * p2);   // (p1^2+p2^2, p1*p2)
                #pragma unroll
                for (int o = 0; o < 8; o++) {
                    int k = j - o;
                    if (k >= 0 && k < KS) {
                        aM[o]  = pfma(pk, CS[GWC(k)], aM[o]);
                        aSX[o] = pfma(sx, CS[GWC(k)], aSX[o]);
                    }
                }
            }
            #pragma unroll
            for (int o = 0; o < 8; o++) {
                hmu[r][c0 + o] = f2_to_b2(aM[o]);
                hsx[r][c0 + o] = f2_to_b2(aSX[o]);
            }
        }
        __syncthreads();
    }

    // ---- vertical pass: 8 warps x 8 rows/thread, 18-tap window, linear hbuf ----
    const int lx = tid & 31;
    const int w  = tid >> 5;
    const int v0 = w << 3;              // warp w -> output rows 8w..8w+7
    const int gx = tx0 + lx;
    const float C1 = 1e-4f;
    const float C2 = 9e-4f;
    float lsum = 0.f;

    ull aM[8], aSX[8];
    #pragma unroll
    for (int o = 0; o < 8; o++) { aM[o] = 0; aSX[o] = 0; }

    #pragma unroll
    for (int rel = 0; rel < 18; rel++) {
        int rr = v0 + rel;
        ull vM  = b2_to_f2(hmu[rr][lx]);
        ull vSX = b2_to_f2(hsx[rr][lx]);
        #pragma unroll
        for (int o = 0; o < 8; o++) {
            int k = rel - o;
            if (k >= 0 && k < KS) {
                aM[o]  = pfma(vM,  CS[GWC(k)], aM[o]);
                aSX[o] = pfma(vSX, CS[GWC(k)], aSX[o]);
            }
        }
    }

    // ---- SSIM map + local sum ----
    #pragma unroll
    for (int o = 0; o < 8; o++) {
        int gy = ty0 + v0 + o;
        if (gy < HOUT && gx < HOUT) {
            float mu1, mu2, xsum, x12;
            up2(aM[o], mu1, mu2);
            up2(aSX[o], xsum, x12);
            float mu1sq = mu1 * mu1;
            float mu2sq = mu2 * mu2;
            float mu12  = mu1 * mu2;
            float sigsum = xsum - mu1sq - mu2sq;  // sigma1_sq + sigma2_sq
            float sig12  = x12  - mu12;
            float v1 = 2.0f * sig12 + C2;
            float v2 = sigsum + C2;
            float num = (2.0f * mu12 + C1) * v1;
            float den = (mu1sq + mu2sq + C1) * v2;
            lsum += __fdividef(num, den);
        }
    }

    // ---- block reduction (8 warps) ----
    #pragma unroll
    for (int off = 16; off > 0; off >>= 1)
        lsum += __shfl_down_sync(0xFFFFFFFFu, lsum, off);
    if (lx == 0) redbuf[w] = lsum;
    __syncthreads();
    if (tid == 0) {
        float v = 0.f;
        #pragma unroll
        for (int ww = 0; ww < 8; ww++) v += redbuf[ww];
        atomicAdd(&g_accum, (double)v);
        __threadfence();
        unsigned int old = atomicAdd(&g_count, 1u);
        if (old == nblocks - 1u) {
            double mean = g_accum / (double)count;
            double loss = 1.0 - mean;
            if (loss < 0.0) loss = 0.0;
            if (loss > 1.0) loss = 1.0;
            out[0] = (float)loss;
            g_accum = 0.0;
            g_count = 0u;
        }
    }
}

extern "C" void kernel_launch(void* const* d_in, const int* in_sizes, int n_in,
                              void* d_out, int out_size) {
    const float* input  = (const float*)d_in[0];
    const float* target = (const float*)d_in[1];
    int sz0 = in_sizes[0], sz1 = in_sizes[1];
    if (sz0 > sz1) {
        const float* t = input; input = target; target = t;
        int ts = sz0; sz0 = sz1; sz1 = ts;
    }
    int n_img = sz0 / (HI * HI);   // 96

    static bool attr_set = false;
    if (!attr_set) {
        cudaFuncSetAttribute(ssim_tile_kernel,
                             cudaFuncAttributeMaxDynamicSharedMemorySize, SMEM_BYTES);
        attr_set = true;
    }

    dim3 grid(NTX, NTY, n_img);
    unsigned int nblocks = NTX * NTY * (unsigned int)n_img;
    long long count = (long long)n_img * HOUT * HOUT;

    ssim_tile_kernel<<<grid, 256, SMEM_BYTES>>>(input, target, (float*)d_out,
                                                count, nblocks);
}

// round 16
// speedup vs baseline: 1.0613x; 1.0086x over previous
#include <cuda_runtime.h>
#include <math.h>

// ---------------- problem constants ----------------
#define KS    11
#define HI    384
#define HO    512
#define HOUT  (HO - KS + 1)     // 502
#define TW    32                // tile width (outputs)
#define TH    64                // tile height (outputs)
#define PW    (TW + KS - 1)     // 42
#define PH    (TH + KS - 1)     // 74
#define SR    42                // s12 ring rows
#define SW    43                // s12 row stride (uint), odd -> conflict-free row walks
#define HS    33                // hbuf row stride (uint2 elements)
#define NTX   ((HOUT + TW - 1) / TW)   // 16
#define NTY   ((HOUT + TH - 1) / TH)   // 8

typedef unsigned long long ull;

// Gaussian weights (sigma=1.5, ks=11), double-normalized, rounded to f32.
#define GW0  0.0010283801f
#define GW1  0.0075987582f
#define GW2  0.0360007722f
#define GW3  0.1093606884f
#define GW4  0.2130055383f
#define GW5  0.2660117256f

__device__ double        g_accum = 0.0;
__device__ unsigned int  g_count = 0;

// ---------------- f32x2 packed helpers ----------------
__device__ __forceinline__ ull splat2(float g) {
    ull r; asm("mov.b64 %0, {%1, %1};" : "=l"(r) : "f"(g)); return r;
}
__device__ __forceinline__ void up2(ull v, float& lo, float& hi) {
    asm("mov.b64 {%0, %1}, %2;" : "=f"(lo), "=f"(hi) : "l"(v));
}
__device__ __forceinline__ ull pfma(ull a, ull b, ull c) {
    ull d; asm("fma.rn.f32x2 %0, %1, %2, %3;" : "=l"(d) : "l"(a), "l"(b), "l"(c)); return d;
}
__device__ __forceinline__ ull pmul(ull a, ull b) {
    ull d; asm("mul.rn.f32x2 %0, %1, %2;" : "=l"(d) : "l"(a), "l"(b)); return d;
}

// bf16x2 <-> f32x2. pack: lo f32 -> bits[0:16), hi f32 -> bits[16:32).
__device__ __forceinline__ unsigned pack_b2(float lo, float hi) {
    unsigned r;
    asm("cvt.rn.bf16x2.f32 %0, %1, %2;" : "=r"(r) : "f"(hi), "f"(lo));
    return r;
}
__device__ __forceinline__ unsigned f2_to_b2(ull v) {
    float lo, hi; up2(v, lo, hi);
    return pack_b2(lo, hi);
}
// unpack: uint bf16x2 -> ull f32x2 (exact: bf16 = top 16 bits of f32)
__device__ __forceinline__ ull b2_to_f2(unsigned v) {
    unsigned lo = v << 16;
    unsigned hi = v & 0xFFFF0000u;
    ull r; asm("mov.b64 %0, {%1, %2};" : "=l"(r) : "r"(lo), "r"(hi));
    return r;
}

#define GWC(k) ((k) < 6 ? (k) : 10 - (k))

// ---- dynamic smem layout (bytes) ----
#define OFF_S12   0                                  // uint  [SR][SW] =  7224 (ring, bf16x2 img1|img2)
#define OFF_H4    (OFF_S12 + SR * SW * 4)            // uint2 [PH][HS] = 19536 (bf16x2 mu | bf16x2 sx)
#define OFF_TBL   (OFF_H4 + PH * HS * 8)
#define OFF_RED   (OFF_TBL + (PH * 4 + PW * 4) * 4)  // tables = 1856
#define SMEM_BYTES (OFF_RED + 64)                    // ~28.7 KB; reg-bound 4 CTAs/SM

// ---------------- single fused kernel ----------------
__global__ void __launch_bounds__(256, 4)
ssim_tile_kernel(const float* __restrict__ input,   // [96, 384, 384]
                 const float* __restrict__ target,  // [96, 512, 512]
                 float* __restrict__ out,
                 long long count, unsigned int nblocks)
{
    extern __shared__ char smem[];
    unsigned (*s12)[SW] = (unsigned (*)[SW])(smem + OFF_S12);
    uint2    (*h4)[HS]  = (uint2 (*)[HS])(smem + OFF_H4);
    int   *riy0 = (int*)  (smem + OFF_TBL);
    int   *riy1 = riy0 + PH;
    float *rwy  = (float*)(riy1 + PH);
    int   *rgy  = (int*)  (rwy + PH);
    int   *cix0 = rgy + PH;
    int   *cix1 = cix0 + PW;
    float *cwx  = (float*)(cix1 + PW);
    int   *cgx  = (int*)  (cwx + PW);
    float *redbuf = (float*)(smem + OFF_RED);

    const int img = blockIdx.z;
    const int ty0 = blockIdx.y * TH;
    const int tx0 = blockIdx.x * TW;
    const int tid = threadIdx.x;

    const float GW[6] = {GW0, GW1, GW2, GW3, GW4, GW5};
    ull CS[6];
    #pragma unroll
    for (int k = 0; k < 6; k++) CS[k] = splat2(GW[k]);

    const float* inp = input  + (size_t)img * (HI * HI);
    const float* tgt = target + (size_t)img * (HO * HO);

    // ---- build bilinear tables ----
    if (tid < PH) {
        int gy = min(ty0 + tid, HO - 1);
        int py = gy * (HI - 1);
        int iy0 = py / (HO - 1);
        riy0[tid] = iy0 * HI;
        riy1[tid] = min(iy0 + 1, HI - 1) * HI;
        rwy[tid]  = (float)(py - iy0 * (HO - 1)) * (1.0f / (float)(HO - 1));
        rgy[tid]  = gy * HO;
    }
    if (tid >= 128 && tid < 128 + PW) {
        int c = tid - 128;
        int gx = min(tx0 + c, HO - 1);
        int px = gx * (HI - 1);
        int ix0 = px / (HO - 1);
        cix0[c] = ix0;
        cix1[c] = min(ix0 + 1, HI - 1);
        cwx[c]  = (float)(px - ix0 * (HO - 1)) * (1.0f / (float)(HO - 1));
        cgx[c]  = gx;
    }
    __syncthreads();

    // ======== two chunks: s12 is a 42-row ring ========
    #pragma unroll 1
    for (int chunk = 0; chunk < 2; chunk++) {
        const int r0    = chunk ? SR : 0;
        const int nrows = chunk ? (PH - SR) : SR;    // 32 : 42

        // ---- load chunk: target direct, img1 bilinear via tables; pack bf16x2 ----
        for (int e = tid; e < nrows * PW; e += 256) {
            int rl = e / PW;            // ring slot
            int c  = e - rl * PW;
            int r  = r0 + rl;           // patch row

            float t2 = tgt[rgy[r] + cgx[c]];

            int   y0 = riy0[r], y1 = riy1[r];
            float wy = rwy[r];
            int   x0 = cix0[c], x1 = cix1[c];
            float wx = cwx[c];

            float a  = inp[y0 + x0];
            float b  = inp[y0 + x1];
            float cc = inp[y1 + x0];
            float d  = inp[y1 + x1];
            float top = a  + (b - a)  * wx;
            float bot = cc + (d - cc) * wx;
            float v1  = top + (bot - top) * wy;

            s12[rl][c] = pack_b2(v1, t2);   // img1 lo, img2 hi
        }
        __syncthreads();

        // ---- horizontal pass: 8 outputs/task, 18-tap sliding window ----
        const int ntasks = nrows * 4;

        for (int t = tid; t < ntasks; t += 256) {
            int g  = t / nrows;         // col group 0..3
            int rl = t - g * nrows;     // ring slot
            int r  = r0 + rl;           // patch row (hbuf row)
            int c0 = g << 3;

            ull aM[8], aSX[8];
            #pragma unroll
            for (int o = 0; o < 8; o++) { aM[o] = 0; aSX[o] = 0; }

            #pragma unroll
            for (int j = 0; j < 18; j++) {
                ull pk = b2_to_f2(s12[rl][c0 + j]);
                float p1, p2;
                up2(pk, p1, p2);
                ull sq = pmul(pk, pk);
                float s1, s2;
                up2(sq, s1, s2);
                ull sx;
                { float xs = s1 + s2, xp = p1 * p2;
                  asm("mov.b64 %0, {%1, %2};" : "=l"(sx) : "f"(xs), "f"(xp)); }
                #pragma unroll
                for (int o = 0; o < 8; o++) {
                    int k = j - o;
                    if (k >= 0 && k < KS) {
                        aM[o]  = pfma(pk, CS[GWC(k)], aM[o]);
                        aSX[o] = pfma(sx, CS[GWC(k)], aSX[o]);
                    }
                }
            }
            #pragma unroll
            for (int o = 0; o < 8; o++) {
                h4[r][c0 + o] = make_uint2(f2_to_b2(aM[o]), f2_to_b2(aSX[o]));
            }
        }
        __syncthreads();
    }

    // ---- vertical pass: 8 warps x 8 rows/thread, 18-tap window, linear hbuf ----
    const int lx = tid & 31;
    const int w  = tid >> 5;
    const int v0 = w << 3;              // warp w -> output rows 8w..8w+7
    const int gx = tx0 + lx;
    const float C1 = 1e-4f;
    const float C2 = 9e-4f;
    float lsum = 0.f;

    ull aM[8], aSX[8];
    #pragma unroll
    for (int o = 0; o < 8; o++) { aM[o] = 0; aSX[o] = 0; }

    #pragma unroll
    for (int rel = 0; rel < 18; rel++) {
        int rr = v0 + rel;
        uint2 v4 = h4[rr][lx];          // one LDS.64
        ull vM  = b2_to_f2(v4.x);
        ull vSX = b2_to_f2(v4.y);
        #pragma unroll
        for (int o = 0; o < 8; o++) {
            int k = rel - o;
            if (k >= 0 && k < KS) {
                aM[o]  = pfma(vM,  CS[GWC(k)], aM[o]);
                aSX[o] = pfma(vSX, CS[GWC(k)], aSX[o]);
            }
        }
    }

    // ---- SSIM map + local sum ----
    #pragma unroll
    for (int o = 0; o < 8; o++) {
        int gy = ty0 + v0 + o;
        if (gy < HOUT && gx < HOUT) {
            float mu1, mu2, xsum, x12;
            up2(aM[o], mu1, mu2);
            up2(aSX[o], xsum, x12);
            float mu1sq = mu1 * mu1;
            float mu2sq = mu2 * mu2;
            float mu12  = mu1 * mu2;
            float sigsum = xsum - mu1sq - mu2sq;  // sigma1_sq + sigma2_sq
            float sig12  = x12  - mu12;
            float v1 = 2.0f * sig12 + C2;
            float v2 = sigsum + C2;
            float num = (2.0f * mu12 + C1) * v1;
            float den = (mu1sq + mu2sq + C1) * v2;
            lsum += __fdividef(num, den);
        }
    }

    // ---- block reduction (8 warps) ----
    #pragma unroll
    for (int off = 16; off > 0; off >>= 1)
        lsum += __shfl_down_sync(0xFFFFFFFFu, lsum, off);
    if (lx == 0) redbuf[w] = lsum;
    __syncthreads();
    if (tid == 0) {
        float v = 0.f;
        #pragma unroll
        for (int ww = 0; ww < 8; ww++) v += redbuf[ww];
        atomicAdd(&g_accum, (double)v);
        __threadfence();
        unsigned int old = atomicAdd(&g_count, 1u);
        if (old == nblocks - 1u) {
            double mean = g_accum / (double)count;
            double loss = 1.0 - mean;
            if (loss < 0.0) loss = 0.0;
            if (loss > 1.0) loss = 1.0;
            out[0] = (float)loss;
            g_accum = 0.0;
            g_count = 0u;
        }
    }
}

extern "C" void kernel_launch(void* const* d_in, const int* in_sizes, int n_in,
                              void* d_out, int out_size) {
    const float* input  = (const float*)d_in[0];
    const float* target = (const float*)d_in[1];
    int sz0 = in_sizes[0], sz1 = in_sizes[1];
    if (sz0 > sz1) {
        const float* t = input; input = target; target = t;
        int ts = sz0; sz0 = sz1; sz1 = ts;
    }
    int n_img = sz0 / (HI * HI);   // 96

    static bool attr_set = false;
    if (!attr_set) {
        cudaFuncSetAttribute(ssim_tile_kernel,
                             cudaFuncAttributeMaxDynamicSharedMemorySize, SMEM_BYTES);
        attr_set = true;
    }

    dim3 grid(NTX, NTY, n_img);
    unsigned int nblocks = NTX * NTY * (unsigned int)n_img;
    long long count = (long long)n_img * HOUT * HOUT;

    ssim_tile_kernel<<<grid, 256, SMEM_BYTES>>>(input, target, (float*)d_out,
                                                count, nblocks);
}

// round 17
// speedup vs baseline: 1.0910x; 1.0279x over previous
#include <cuda_runtime.h>
#include <math.h>

// ---------------- problem constants ----------------
#define KS    11
#define HI    384
#define HO    512
#define HOUT  (HO - KS + 1)     // 502
#define TW    32                // tile width (outputs)
#define TH    64                // tile height (outputs)
#define PW    (TW + KS - 1)     // 42
#define PH    (TH + KS - 1)     // 74
#define SW    43                // s12 row stride (ull), odd -> conflict-free row walks
#define HS    33                // hbuf row stride (uint2 elements)
#define NTX   ((HOUT + TW - 1) / TW)   // 16
#define NTY   ((HOUT + TH - 1) / TH)   // 8
#define HTASKS (PH * 4)         // 296 tasks, 8 output cols each

typedef unsigned long long ull;

// Gaussian weights (sigma=1.5, ks=11), double-normalized, rounded to f32.
#define GW0  0.0010283801f
#define GW1  0.0075987582f
#define GW2  0.0360007722f
#define GW3  0.1093606884f
#define GW4  0.2130055383f
#define GW5  0.2660117256f

__device__ double        g_accum = 0.0;
__device__ unsigned int  g_count = 0;

// ---------------- f32x2 packed helpers ----------------
__device__ __forceinline__ ull splat2(float g) {
    ull r; asm("mov.b64 %0, {%1, %1};" : "=l"(r) : "f"(g)); return r;
}
__device__ __forceinline__ void up2(ull v, float& lo, float& hi) {
    asm("mov.b64 {%0, %1}, %2;" : "=f"(lo), "=f"(hi) : "l"(v));
}
__device__ __forceinline__ ull pk2(float lo, float hi) {
    ull r; asm("mov.b64 %0, {%1, %2};" : "=l"(r) : "f"(lo), "f"(hi)); return r;
}
__device__ __forceinline__ ull pfma(ull a, ull b, ull c) {
    ull d; asm("fma.rn.f32x2 %0, %1, %2, %3;" : "=l"(d) : "l"(a), "l"(b), "l"(c)); return d;
}
__device__ __forceinline__ ull pmul(ull a, ull b) {
    ull d; asm("mul.rn.f32x2 %0, %1, %2;" : "=l"(d) : "l"(a), "l"(b)); return d;
}

// bf16x2 pack: lo f32 -> bits[0:16), hi f32 -> bits[16:32).
__device__ __forceinline__ unsigned f2_to_b2(ull v) {
    float lo, hi; up2(v, lo, hi);
    unsigned r;
    asm("cvt.rn.bf16x2.f32 %0, %1, %2;" : "=r"(r) : "f"(hi), "f"(lo));
    return r;
}
// unpack: uint bf16x2 -> ull f32x2 (exact: bf16 = top 16 bits of f32)
__device__ __forceinline__ ull b2_to_f2(unsigned v) {
    unsigned lo = v << 16;
    unsigned hi = v & 0xFFFF0000u;
    ull r; asm("mov.b64 %0, {%1, %2};" : "=l"(r) : "r"(lo), "r"(hi));
    return r;
}

#define GWC(k) ((k) < 6 ? (k) : 10 - (k))

// ---- dynamic smem layout (bytes) ----
#define OFF_S12   0                                  // ull   [PH][SW] = 25456 (f32x2 img1|img2)
#define OFF_H4    (OFF_S12 + PH * SW * 8)            // uint2 [PH][HS] = 19536 (bf16x2 mu | bf16x2 sx)
#define OFF_TBL   (OFF_H4 + PH * HS * 8)
#define OFF_RED   (OFF_TBL + (PH * 4 + PW * 4) * 4)  // tables = 1856
#define SMEM_BYTES (OFF_RED + 64)                    // ~46.9 KB -> 4 CTAs/SM

// ---------------- single fused kernel ----------------
__global__ void __launch_bounds__(256, 4)
ssim_tile_kernel(const float* __restrict__ input,   // [96, 384, 384]
                 const float* __restrict__ target,  // [96, 512, 512]
                 float* __restrict__ out,
                 long long count, unsigned int nblocks)
{
    extern __shared__ char smem[];
    ull   (*s12)[SW] = (ull (*)[SW])(smem + OFF_S12);
    uint2 (*h4)[HS]  = (uint2 (*)[HS])(smem + OFF_H4);
    int   *riy0 = (int*)  (smem + OFF_TBL);
    int   *riy1 = riy0 + PH;
    float *rwy  = (float*)(riy1 + PH);
    int   *rgy  = (int*)  (rwy + PH);
    int   *cix0 = rgy + PH;
    int   *cix1 = cix0 + PW;
    float *cwx  = (float*)(cix1 + PW);
    int   *cgx  = (int*)  (cwx + PW);
    float *redbuf = (float*)(smem + OFF_RED);

    const int img = blockIdx.z;
    const int ty0 = blockIdx.y * TH;
    const int tx0 = blockIdx.x * TW;
    const int tid = threadIdx.x;

    const float GW[6] = {GW0, GW1, GW2, GW3, GW4, GW5};
    ull CS[6];
    #pragma unroll
    for (int k = 0; k < 6; k++) CS[k] = splat2(GW[k]);

    const float* inp = input  + (size_t)img * (HI * HI);
    const float* tgt = target + (size_t)img * (HO * HO);

    // ---- build bilinear tables ----
    if (tid < PH) {
        int gy = min(ty0 + tid, HO - 1);
        int py = gy * (HI - 1);
        int iy0 = py / (HO - 1);
        riy0[tid] = iy0 * HI;
        riy1[tid] = min(iy0 + 1, HI - 1) * HI;
        rwy[tid]  = (float)(py - iy0 * (HO - 1)) * (1.0f / (float)(HO - 1));
        rgy[tid]  = gy * HO;
    }
    if (tid >= 128 && tid < 128 + PW) {
        int c = tid - 128;
        int gx = min(tx0 + c, HO - 1);
        int px = gx * (HI - 1);
        int ix0 = px / (HO - 1);
        cix0[c] = ix0;
        cix1[c] = min(ix0 + 1, HI - 1);
        cwx[c]  = (float)(px - ix0 * (HO - 1)) * (1.0f / (float)(HO - 1));
        cgx[c]  = gx;
    }
    __syncthreads();

    // ---- load full 74x42 patch: target direct, img1 bilinear via tables ----
    for (int e = tid; e < PH * PW; e += 256) {
        int r = e / PW;
        int c = e - r * PW;

        float t2 = tgt[rgy[r] + cgx[c]];

        int   y0 = riy0[r], y1 = riy1[r];
        float wy = rwy[r];
        int   x0 = cix0[c], x1 = cix1[c];
        float wx = cwx[c];

        float a  = inp[y0 + x0];
        float b  = inp[y0 + x1];
        float cc = inp[y1 + x0];
        float d  = inp[y1 + x1];
        float top = a  + (b - a)  * wx;
        float bot = cc + (d - cc) * wx;
        float v1  = top + (bot - top) * wy;

        s12[r][c] = pk2(v1, t2);
    }
    __syncthreads();

    // ---- horizontal pass: 8 outputs/task, 18-tap sliding window,
    //      consecutive lanes walk consecutive rows (conflict-free) ----
    for (int t = tid; t < HTASKS; t += 256) {
        int g  = t / PH;            // col group 0..3
        int r  = t - g * PH;        // row 0..73
        int c0 = g << 3;

        ull aM[8], aSX[8];
        #pragma unroll
        for (int o = 0; o < 8; o++) { aM[o] = 0; aSX[o] = 0; }

        #pragma unroll
        for (int j = 0; j < 18; j++) {
            ull pk = s12[r][c0 + j];
            float p1, p2;
            up2(pk, p1, p2);
            ull sq = pmul(pk, pk);
            float s1, s2;
            up2(sq, s1, s2);
            ull sx;
            { float xs = s1 + s2, xp = p1 * p2;
              asm("mov.b64 %0, {%1, %2};" : "=l"(sx) : "f"(xs), "f"(xp)); }
            #pragma unroll
            for (int o = 0; o < 8; o++) {
                int k = j - o;
                if (k >= 0 && k < KS) {
                    aM[o]  = pfma(pk, CS[GWC(k)], aM[o]);
                    aSX[o] = pfma(sx, CS[GWC(k)], aSX[o]);
                }
            }
        }
        #pragma unroll
        for (int o = 0; o < 8; o++) {
            h4[r][c0 + o] = make_uint2(f2_to_b2(aM[o]), f2_to_b2(aSX[o]));
        }
    }
    __syncthreads();

    // ---- vertical pass: 8 warps x 8 rows/thread, 18-tap window,
    //      linear hbuf, prefetched LDS ----
    const int lx = tid & 31;
    const int w  = tid >> 5;
    const int v0 = w << 3;              // warp w -> output rows 8w..8w+7
    const int gx = tx0 + lx;
    const float C1 = 1e-4f;
    const float C2 = 9e-4f;
    float lsum = 0.f;

    ull aM[8], aSX[8];
    #pragma unroll
    for (int o = 0; o < 8; o++) { aM[o] = 0; aSX[o] = 0; }

    uint2 v4 = h4[v0][lx];

    #pragma unroll
    for (int rel = 0; rel < 18; rel++) {
        uint2 n4 = make_uint2(0u, 0u);
        if (rel < 17) n4 = h4[v0 + rel + 1][lx];   // prefetch next row
        ull vM  = b2_to_f2(v4.x);
        ull vSX = b2_to_f2(v4.y);
        #pragma unroll
        for (int o = 0; o < 8; o++) {
            int k = rel - o;
            if (k >= 0 && k < KS) {
                aM[o]  = pfma(vM,  CS[GWC(k)], aM[o]);
                aSX[o] = pfma(vSX, CS[GWC(k)], aSX[o]);
            }
        }
        v4 = n4;
    }

    // ---- SSIM map + local sum ----
    #pragma unroll
    for (int o = 0; o < 8; o++) {
        int gy = ty0 + v0 + o;
        if (gy < HOUT && gx < HOUT) {
            float mu1, mu2, xsum, x12;
            up2(aM[o], mu1, mu2);
            up2(aSX[o], xsum, x12);
            float mu1sq = mu1 * mu1;
            float mu2sq = mu2 * mu2;
            float mu12  = mu1 * mu2;
            float sigsum = xsum - mu1sq - mu2sq;  // sigma1_sq + sigma2_sq
            float sig12  = x12  - mu12;
            float v1 = 2.0f * sig12 + C2;
            float v2 = sigsum + C2;
            float num = (2.0f * mu12 + C1) * v1;
            float den = (mu1sq + mu2sq + C1) * v2;
            lsum += __fdividef(num, den);
        }
    }

    // ---- block reduction (8 warps) ----
    #pragma unroll
    for (int off = 16; off > 0; off >>= 1)
        lsum += __shfl_down_sync(0xFFFFFFFFu, lsum, off);
    if (lx == 0) redbuf[w] = lsum;
    __syncthreads();
    if (tid == 0) {
        float v = 0.f;
        #pragma unroll
        for (int ww = 0; ww < 8; ww++) v += redbuf[ww];
        atomicAdd(&g_accum, (double)v);
        __threadfence();
        unsigned int old = atomicAdd(&g_count, 1u);
        if (old == nblocks - 1u) {
            double mean = g_accum / (double)count;
            double loss = 1.0 - mean;
            if (loss < 0.0) loss = 0.0;
            if (loss > 1.0) loss = 1.0;
            out[0] = (float)loss;
            g_accum = 0.0;
            g_count = 0u;
        }
    }
}

extern "C" void kernel_launch(void* const* d_in, const int* in_sizes, int n_in,
                              void* d_out, int out_size) {
    const float* input  = (const float*)d_in[0];
    const float* target = (const float*)d_in[1];
    int sz0 = in_sizes[0], sz1 = in_sizes[1];
    if (sz0 > sz1) {
        const float* t = input; input = target; target = t;
        int ts = sz0; sz0 = sz1; sz1 = ts;
    }
    int n_img = sz0 / (HI * HI);   // 96

    static bool attr_set = false;
    if (!attr_set) {
        cudaFuncSetAttribute(ssim_tile_kernel,
                             cudaFuncAttributeMaxDynamicSharedMemorySize, SMEM_BYTES);
        attr_set = true;
    }

    dim3 grid(NTX, NTY, n_img);
    unsigned int nblocks = NTX * NTY * (unsigned int)n_img;
    long long count = (long long)n_img * HOUT * HOUT;

    ssim_tile_kernel<<<grid, 256, SMEM_BYTES>>>(input, target, (float*)d_out,
                                                count, nblocks);
}